// round 1
// baseline (speedup 1.0000x reference)
#include <cuda_runtime.h>
#include <cstdint>

#define N_NODES   50000
#define IN_FEAT   128
#define OUT_FEAT  128
#define NB        16
#define SI        8
#define SO        8
#define W_PER_REL (NB * SI * SO)   // 1024

// ---------------------------------------------------------------------------
// Vectorized global float4 reduction (sm_90+): one 16B atomic instead of 4x4B
// ---------------------------------------------------------------------------
__device__ __forceinline__ void red_add_v4(float* addr, float4 v) {
    asm volatile("red.global.add.v4.f32 [%0], {%1, %2, %3, %4};"
                 :: "l"(addr), "f"(v.x), "f"(v.y), "f"(v.z), "f"(v.w)
                 : "memory");
}

// ---------------------------------------------------------------------------
// Kernel A: d_out = h @ loop_weight   (also initializes d_out fully)
// One block handles ROWS_PER_BLOCK rows; 128 threads = one output column each.
// loop_weight (64KB) stays hot in L1 across the k-loop.
// ---------------------------------------------------------------------------
#define ROWS_PER_BLOCK 4
__global__ void loop_gemm_kernel(const float* __restrict__ h,
                                 const float* __restrict__ lw,
                                 float* __restrict__ out) {
    __shared__ float xs[ROWS_PER_BLOCK][IN_FEAT];
    int r0 = blockIdx.x * ROWS_PER_BLOCK;
    int tid = threadIdx.x;  // 0..127 = output column

    int nrows = N_NODES - r0;
    if (nrows > ROWS_PER_BLOCK) nrows = ROWS_PER_BLOCK;

    for (int r = 0; r < nrows; r++)
        xs[r][tid] = h[(size_t)(r0 + r) * IN_FEAT + tid];
    __syncthreads();

    float acc[ROWS_PER_BLOCK];
#pragma unroll
    for (int r = 0; r < ROWS_PER_BLOCK; r++) acc[r] = 0.0f;

#pragma unroll 4
    for (int k = 0; k < IN_FEAT; k++) {
        float w = __ldg(lw + (size_t)k * OUT_FEAT + tid);
#pragma unroll
        for (int r = 0; r < ROWS_PER_BLOCK; r++)
            acc[r] = fmaf(xs[r][k], w, acc[r]);
    }

    for (int r = 0; r < nrows; r++)
        out[(size_t)(r0 + r) * OUT_FEAT + tid] = acc[r];
}

// ---------------------------------------------------------------------------
// Kernel B: one warp per edge.
//   lane l computes output columns 4l..4l+3  (basis block b = l>>1, o0 = (l&1)*4)
//   msg[o] = sum_i x[src, b*8+i] * W[etype, b, i, o]
//   red.global.add.v4( out + dst*128 + 4l, msg * norm[dst] )
// ---------------------------------------------------------------------------
__global__ void edge_kernel(const float* __restrict__ h,
                            const float* __restrict__ norm,
                            const float* __restrict__ weight,
                            const int*   __restrict__ src,
                            const int*   __restrict__ dst,
                            const int*   __restrict__ etype,
                            float* __restrict__ out,
                            int nedges) {
    int gw   = (blockIdx.x * blockDim.x + threadIdx.x) >> 5;  // edge id
    int lane = threadIdx.x & 31;
    if (gw >= nedges) return;

    int s = __ldg(src + gw);
    int d = __ldg(dst + gw);
    int t = __ldg(etype + gw);
    float nrm = __ldg(norm + d);

    int b  = lane >> 1;          // basis block 0..15
    int o0 = (lane & 1) * 4;     // output offset within block: 0 or 4

    // 8 input features of this basis block (two lanes share -> broadcast)
    const float4* xp = reinterpret_cast<const float4*>(h + (size_t)s * IN_FEAT + b * SI);
    float4 xa = __ldg(xp);
    float4 xb = __ldg(xp + 1);
    float x[8] = {xa.x, xa.y, xa.z, xa.w, xb.x, xb.y, xb.z, xb.w};

    // W block: weight[t, b, i, o0..o0+3], i = 0..7 ; stride 8 floats per i
    const float* wb = weight + (size_t)t * W_PER_REL + b * (SI * SO) + o0;

    float4 acc = make_float4(0.f, 0.f, 0.f, 0.f);
#pragma unroll
    for (int i = 0; i < SI; i++) {
        float4 w = __ldg(reinterpret_cast<const float4*>(wb + i * SO));
        acc.x = fmaf(x[i], w.x, acc.x);
        acc.y = fmaf(x[i], w.y, acc.y);
        acc.z = fmaf(x[i], w.z, acc.z);
        acc.w = fmaf(x[i], w.w, acc.w);
    }

    acc.x *= nrm; acc.y *= nrm; acc.z *= nrm; acc.w *= nrm;

    red_add_v4(out + (size_t)d * OUT_FEAT + lane * 4, acc);
}

// ---------------------------------------------------------------------------
// Kernel C: in-place ReLU over d_out (N*128 floats), float4 vectorized.
// ---------------------------------------------------------------------------
__global__ void relu_kernel(float4* __restrict__ out, int n4) {
    int i = blockIdx.x * blockDim.x + threadIdx.x;
    if (i >= n4) return;
    float4 v = out[i];
    v.x = fmaxf(v.x, 0.f);
    v.y = fmaxf(v.y, 0.f);
    v.z = fmaxf(v.z, 0.f);
    v.w = fmaxf(v.w, 0.f);
    out[i] = v;
}

// ---------------------------------------------------------------------------
// Launch: A (GEMM init) -> B (edge scatter) -> C (ReLU)
// Inputs (metadata order): h, norm, weight, loop_weight, src, dst, etype
// ---------------------------------------------------------------------------
extern "C" void kernel_launch(void* const* d_in, const int* in_sizes, int n_in,
                              void* d_out, int out_size) {
    const float* h      = (const float*)d_in[0];
    const float* norm   = (const float*)d_in[1];
    const float* weight = (const float*)d_in[2];
    const float* lw     = (const float*)d_in[3];
    const int*   src    = (const int*)d_in[4];
    const int*   dst    = (const int*)d_in[5];
    const int*   etype  = (const int*)d_in[6];
    float* out = (float*)d_out;

    int nedges = in_sizes[4];

    // A: self-loop GEMM, fully overwrites d_out
    {
        int blocks = (N_NODES + ROWS_PER_BLOCK - 1) / ROWS_PER_BLOCK;
        loop_gemm_kernel<<<blocks, 128>>>(h, lw, out);
    }
    // B: per-edge messages, norm-scaled, vector red into d_out
    {
        int threads = 256;                       // 8 warps -> 8 edges / block
        int warps_per_block = threads / 32;
        int blocks = (nedges + warps_per_block - 1) / warps_per_block;
        edge_kernel<<<blocks, threads>>>(h, norm, weight, src, dst, etype, out, nedges);
    }
    // C: ReLU
    {
        int n4 = N_NODES * OUT_FEAT / 4;
        int threads = 256;
        int blocks = (n4 + threads - 1) / threads;
        relu_kernel<<<blocks, threads>>>((float4*)out, n4);
    }
}